// round 11
// baseline (speedup 1.0000x reference)
#include <cuda_runtime.h>
#include <cstddef>
#include <cstdint>

// Single-pass decoupled-chaining scan for c_t = a_t * c_{t-1} + b_t, c_{-1}=0.
// input  : [B, T, 2*UNITS] fp32   (a = [:,:,:UNITS], b = [:,:,UNITS:])
// output : [B, T, UNITS]
//
// R11 = R9 protocol + WIDER BLOCKS: same tile (CHUNK_T=64) split over 512
// threads (SEGS=16 x LSEG=4) instead of 256 (8x8). Halves the per-thread
// serial FMA chain and register payload (data regs 64 -> 32), so 2 blocks/SM
// = 32 warps/SM (occ 50%) -- the most streaming warps of any round WITHOUT
// shrinking the chunk (which sank R4). Tests whether the stubborn 76-78%
// DRAM plateau is warp-count-limited or the stream-mix ceiling.
// Flags remain consumer-reset (graph-replay safe, no prologue kernel).

#define T_C      2048
#define UNITS_C  2048
#define B_MAX    16

constexpr int LANES   = 32;
constexpr int SEGS    = 16;
constexpr int LSEG    = 4;                    // timesteps per thread
constexpr int CHUNK_T = SEGS * LSEG;          // 64
constexpr int CH      = T_C / CHUNK_T;        // 32
constexpr int VG      = UNITS_C / (LANES*4);  // 16 vec-groups per batch row
constexpr int NROWS   = B_MAX * VG * CH;      // 8192 carry rows

__device__ float4   g_prefix[NROWS][LANES];
__device__ unsigned g_flag  [NROWS][LANES];   // zero-init at load; self-resetting

__device__ __forceinline__ float4 f4_fma(float4 a, float4 x, float4 b)
{   // a*x + b
    float4 r;
    r.x = fmaf(a.x, x.x, b.x); r.y = fmaf(a.y, x.y, b.y);
    r.z = fmaf(a.z, x.z, b.z); r.w = fmaf(a.w, x.w, b.w);
    return r;
}
__device__ __forceinline__ float4 f4_mul(float4 a, float4 b)
{
    float4 r; r.x=a.x*b.x; r.y=a.y*b.y; r.z=a.z*b.z; r.w=a.w*b.w; return r;
}

__global__ void __launch_bounds__(512, 2)
tempo_scan_kernel(const float* __restrict__ in, float* __restrict__ out, int nbatch)
{
    const int lane = threadIdx.x & 31;
    const int seg  = threadIdx.x >> 5;         // 0..15

    // chunk index in the HIGH bits of blockIdx so chunk-0 blocks dispatch first
    const int gpb = nbatch * VG;
    const int p   = blockIdx.x / gpb;          // time chunk
    const int r   = blockIdx.x % gpb;
    const int g   = r / VG;                    // batch
    const int vg  = r % VG;                    // vec-group (32 float4 lanes)

    const int t0 = p * CHUNK_T + seg * LSEG;

    // 32-bit float4-granular offsets (tensor < 2^27 float4s)
    constexpr unsigned RS4 = (2 * UNITS_C) / 4;   // input row stride: 1024 f4
    constexpr unsigned OS4 = UNITS_C / 4;         // output row stride: 512 f4
    const unsigned ufo = (unsigned)(vg * LANES + lane);
    const unsigned ain = ((unsigned)g * T_C + (unsigned)t0) * RS4 + ufo;
    const unsigned aou = ((unsigned)g * T_C + (unsigned)t0) * OS4 + ufo;

    const float4* pa = (const float4*)in + ain;
    const float4* pb = pa + (UNITS_C / 4);
    float4*       po = (float4*)out + aou;

    // ---- phase 1: issue all loads immediately (this is ALL the HBM read) ----
    float4 A[LSEG], C[LSEG];
    #pragma unroll
    for (int i = 0; i < LSEG; ++i) {
        A[i] = __ldcs(pa + i * RS4);
        C[i] = __ldcs(pb + i * RS4);
    }

    // local scan with zero prefix: C[i] = c_local_i, A[i] = prod_{j<=i} a_j
    #pragma unroll
    for (int i = 1; i < LSEG; ++i) {
        C[i] = f4_fma(A[i], C[i-1], C[i]);
        A[i] = f4_mul(A[i], A[i-1]);
    }

    // ---- intra-block segment scan via smem ----
    __shared__ float4 sA[SEGS][LANES];
    __shared__ float4 sC[SEGS][LANES];
    __shared__ float4 sP[LANES];

    sA[seg][lane] = A[LSEG-1];
    sC[seg][lane] = C[LSEG-1];
    __syncthreads();

    // exclusive prefix over segments 0..seg-1:  (EA, EC)
    float4 EA = make_float4(1.f,1.f,1.f,1.f);
    float4 EC = make_float4(0.f,0.f,0.f,0.f);
    #pragma unroll
    for (int j = 0; j < SEGS-1; ++j) {
        if (j < seg) {
            float4 Aj = sA[j][lane], Cj = sC[j][lane];
            EC = f4_fma(Aj, EC, Cj);     // apply segment j after current prefix
            EA = f4_mul(Aj, EA);
        }
    }

    // ---- fetch predecessor chunk's carry (warp 0), broadcast via smem ----
    if (seg == 0) {
        float4 P = make_float4(0.f,0.f,0.f,0.f);
        if (p > 0) {
            const int rprev = ((p-1) * nbatch + g) * VG + vg;
            unsigned* f = &g_flag[rprev][lane];
            unsigned v;
            asm volatile("ld.global.acquire.gpu.b32 %0, [%1];"
                         : "=r"(v) : "l"(f) : "memory");
            while (!v) {
                __nanosleep(20);
                asm volatile("ld.global.acquire.gpu.b32 %0, [%1];"
                             : "=r"(v) : "l"(f) : "memory");
            }
            P = g_prefix[rprev][lane];
            // consumer-reset: restore "flags are zero" for the next graph
            // replay (sole consumer; kernel boundary orders across launches).
            asm volatile("st.global.relaxed.gpu.b32 [%0], %1;"
                         :: "l"(f), "r"(0u) : "memory");
        }
        sP[lane] = P;
    }
    __syncthreads();

    // full c-prefix at this thread's segment start
    const float4 P  = sP[lane];
    const float4 Pc = f4_fma(EA, P, EC);

    // ---- publish own carry FIRST (shortens the cross-chunk chain) ----
    if (seg == SEGS-1 && p < CH-1) {
        const int rcur = (p * nbatch + g) * VG + vg;
        float4 carry = f4_fma(A[LSEG-1], Pc, C[LSEG-1]);
        g_prefix[rcur][lane] = carry;
        asm volatile("st.global.release.gpu.b32 [%0], %1;"
                     :: "l"(&g_flag[rcur][lane]), "r"(1u) : "memory");
    }

    // ---- finalize + store outputs ----
    #pragma unroll
    for (int i = 0; i < LSEG; ++i) {
        float4 cf = f4_fma(A[i], Pc, C[i]);
        __stcs(po + i * OS4, cf);
    }
}

extern "C" void kernel_launch(void* const* d_in, const int* in_sizes, int n_in,
                              void* d_out, int out_size)
{
    const float* in  = (const float*)d_in[0];
    float*       out = (float*)d_out;

    const int batch = in_sizes[0] / (T_C * 2 * UNITS_C);

    const int grid = CH * batch * VG;      // 8192 for B=16
    tempo_scan_kernel<<<grid, 512>>>(in, out, batch);
}